// round 5
// baseline (speedup 1.0000x reference)
#include <cuda_runtime.h>

#define DI __device__ __forceinline__
#define NB 64

// ---------------- scratch (static device globals; no allocation) ----------------
__device__ float g_e1[NB*32*128*128];   // e1 out
__device__ float g_e2[NB*64*64*64];     // e2 out
__device__ float g_d1[NB*32*64*64];     // d1 out
__device__ float g_d2[NB*64*128*128];   // d2 out
__device__ float g_enorm[512];

// ---------------- ||e||^2 (sequential, separate mul/add: strict reduce) ----------------
__global__ void k_enorm(const float* __restrict__ emb) {
    int k = threadIdx.x;            // blockDim = 512
    float s = 0.f;
    for (int c = 0; c < 64; c++) {
        float v = emb[k*64 + c];
        s = __fadd_rn(s, __fmul_rn(v, v));
    }
    g_enorm[k] = s;
}

// ---------------- e1: conv 1->32, k4 s2 p1, 256->128, ReLU ----------------
// chain order per output: (kh, kw) ascending, single fmaf chain
// grid (128=oh, 4=ocg, 64=n), block 128 = ow; 8 oc per thread
__global__ void __launch_bounds__(128) k_e1(const float* __restrict__ x,
                                            const float* __restrict__ w,
                                            const float* __restrict__ b) {
    __shared__ float ws[128];       // 8 oc x 16
    int ow = threadIdx.x;
    int oh = blockIdx.x;
    int ocg = blockIdx.y;
    int n  = blockIdx.z;
    if (ow < 128) { ws[ow] = w[ocg*128 + ow]; }
    __syncthreads();

    const float* xin = x + n*65536;
    float acc[8];
    #pragma unroll
    for (int i = 0; i < 8; i++) acc[i] = 0.f;

    #pragma unroll
    for (int kh = 0; kh < 4; kh++) {
        int ih = oh*2 - 1 + kh;
        if ((unsigned)ih >= 256u) continue;
        const float* row = xin + ih*256;
        #pragma unroll
        for (int kw = 0; kw < 4; kw++) {
            int iw = ow*2 - 1 + kw;
            if ((unsigned)iw >= 256u) continue;
            float xv = __ldg(row + iw);
            #pragma unroll
            for (int i = 0; i < 8; i++)
                acc[i] = fmaf(xv, ws[i*16 + kh*4 + kw], acc[i]);
        }
    }
    #pragma unroll
    for (int i = 0; i < 8; i++) {
        int oc = ocg*8 + i;
        float v = __fadd_rn(acc[i], __ldg(b + oc));
        g_e1[((n*32 + oc)*128 + oh)*128 + ow] = v > 0.f ? v : 0.f;
    }
}

// ---------------- e2: conv 32->64, k4 s2 p1, 128->64, ReLU ----------------
// chain per output: (kh, kw, ic) ic-innermost single fmaf chain (zero-padded
// taps contribute fmaf(0,w,acc)==acc, bitwise identical to skipping).
// block 64: tid&15 = owg (4 ow each), tid>>4 = r (4 rows); grid (16, 8=ocg, 64=n)
__global__ void __launch_bounds__(64) k_e2(const float* __restrict__ w,
                                           const float* __restrict__ b) {
    __shared__ float ws[4096];      // 8 oc x 32 ic x 16
    int tid = threadIdx.x;
    int ocg = blockIdx.y;
    int n  = blockIdx.z;
    for (int t = tid; t < 4096; t += 64) ws[t] = w[ocg*4096 + t];
    __syncthreads();

    int owg = tid & 15, r = tid >> 4;
    int oh = blockIdx.x*4 + r;
    int ow0 = owg*4;

    const float* inn = g_e1 + n*(32*16384);
    float acc[8][4];
    #pragma unroll
    for (int i = 0; i < 8; i++)
        #pragma unroll
        for (int j = 0; j < 4; j++) acc[i][j] = 0.f;

    #pragma unroll
    for (int kh = 0; kh < 4; kh++) {
        int ih = oh*2 - 1 + kh;
        bool hok = (unsigned)ih < 128u;
        #pragma unroll
        for (int kw = 0; kw < 4; kw++) {
            int iwb = ow0*2 - 1 + kw;
            bool wok[4];
            #pragma unroll
            for (int j = 0; j < 4; j++) wok[j] = hok && ((unsigned)(iwb + 2*j) < 128u);
            const float* ip = inn + ih*128 + iwb;
            int wbase = kh*4 + kw;
            #pragma unroll 4
            for (int ic = 0; ic < 32; ic++) {
                float xv[4];
                #pragma unroll
                for (int j = 0; j < 4; j++)
                    xv[j] = wok[j] ? __ldg(ip + ic*16384 + 2*j) : 0.f;
                #pragma unroll
                for (int i = 0; i < 8; i++) {
                    float wv = ws[i*512 + ic*16 + wbase];
                    #pragma unroll
                    for (int j = 0; j < 4; j++)
                        acc[i][j] = fmaf(xv[j], wv, acc[i][j]);
                }
            }
        }
    }
    #pragma unroll
    for (int i = 0; i < 8; i++) {
        int oc = ocg*8 + i;
        float bb = __ldg(b + oc);
        float* op = g_e2 + ((n*64 + oc)*64 + oh)*64 + ow0;
        #pragma unroll
        for (int j = 0; j < 4; j++) {
            float v = __fadd_rn(acc[i][j], bb);
            op[j] = v > 0.f ? v : 0.f;
        }
    }
}

// ---------------- e3: conv 64->64, k3 s1 p1, 64x64, ReLU ----------------
// chain per output: (kh, kw, ic) ic-innermost single fmaf chain (zero-padded).
// block 64: tid&15 = owg (4 ow each), tid>>4 = r (4 rows); grid (16, 8=ocg, 64=n)
__global__ void __launch_bounds__(64) k_e3(const float* __restrict__ w,
                                           const float* __restrict__ b,
                                           float* __restrict__ ze) {
    __shared__ float ws[4608];      // 8 oc x 64 ic x 9
    int tid = threadIdx.x;
    int ocg = blockIdx.y;
    int n  = blockIdx.z;
    for (int t = tid; t < 4608; t += 64) ws[t] = w[ocg*4608 + t];
    __syncthreads();

    int owg = tid & 15, r = tid >> 4;
    int oh = blockIdx.x*4 + r;
    int ow0 = owg*4;

    const float* inn = g_e2 + n*(64*4096);
    float acc[8][4];
    #pragma unroll
    for (int i = 0; i < 8; i++)
        #pragma unroll
        for (int j = 0; j < 4; j++) acc[i][j] = 0.f;

    #pragma unroll
    for (int kh = 0; kh < 3; kh++) {
        int ih = oh - 1 + kh;
        bool hok = (unsigned)ih < 64u;
        #pragma unroll
        for (int kw = 0; kw < 3; kw++) {
            int iwb = ow0 - 1 + kw;
            bool wok[4];
            #pragma unroll
            for (int j = 0; j < 4; j++) wok[j] = hok && ((unsigned)(iwb + j) < 64u);
            const float* ip = inn + ih*64 + iwb;
            int wbase = kh*3 + kw;
            #pragma unroll 4
            for (int ic = 0; ic < 64; ic++) {
                float xv[4];
                #pragma unroll
                for (int j = 0; j < 4; j++)
                    xv[j] = wok[j] ? __ldg(ip + ic*4096 + j) : 0.f;
                #pragma unroll
                for (int i = 0; i < 8; i++) {
                    float wv = ws[i*576 + ic*9 + wbase];
                    #pragma unroll
                    for (int j = 0; j < 4; j++)
                        acc[i][j] = fmaf(xv[j], wv, acc[i][j]);
                }
            }
        }
    }
    #pragma unroll
    for (int i = 0; i < 8; i++) {
        int oc = ocg*8 + i;
        float bb = __ldg(b + oc);
        float* op = ze + ((n*64 + oc)*64 + oh)*64 + ow0;
        #pragma unroll
        for (int j = 0; j < 4; j++) {
            float v = __fadd_rn(acc[i][j], bb);
            op[j] = v > 0.f ? v : 0.f;
        }
    }
}

// ---------------- VQ: argmin over 512 codes, write zq ----------------
// dist replicates reference formula: (||z||^2 - 2*(z.e)) + ||e||^2 in fp32.
// block 128 thr, 2 locations/thread; grid 1024
__global__ void __launch_bounds__(128) k_vq(const float* __restrict__ ze,
                                            const float* __restrict__ emb,
                                            float* __restrict__ zq) {
    __shared__ float4 se4[128*16];   // 128 codes x 64 floats
    __shared__ float  sn[128];
    int tid = threadIdx.x;
    int loc0 = blockIdx.x*256 + tid;
    int loc1 = loc0 + 128;
    int n0 = loc0 >> 12, hw0 = loc0 & 4095;
    int n1 = loc1 >> 12, hw1 = loc1 & 4095;

    float z0[64], z1[64];
    const float* p0 = ze + n0*(64*4096) + hw0;
    const float* p1 = ze + n1*(64*4096) + hw1;
    #pragma unroll
    for (int c = 0; c < 64; c++) {
        z0[c] = __ldg(p0 + c*4096);
        z1[c] = __ldg(p1 + c*4096);
    }
    float A0 = 0.f, A1 = 0.f;
    #pragma unroll
    for (int c = 0; c < 64; c++) {
        A0 = __fadd_rn(A0, __fmul_rn(z0[c], z0[c]));
        A1 = __fadd_rn(A1, __fmul_rn(z1[c], z1[c]));
    }

    float best0 = 3.4e38f, best1 = 3.4e38f;
    int bi0 = 0, bi1 = 0;
    for (int kc = 0; kc < 4; kc++) {
        __syncthreads();
        const float4* src = (const float4*)(emb + kc*128*64);
        for (int t = tid; t < 2048; t += 128) se4[t] = __ldg(src + t);
        sn[tid] = g_enorm[kc*128 + tid];
        __syncthreads();

        for (int kk = 0; kk < 128; kk++) {
            float d0 = 0.f, d1 = 0.f;
            #pragma unroll
            for (int c4 = 0; c4 < 16; c4++) {
                float4 e = se4[kk*16 + c4];
                d0 = fmaf(z0[4*c4+0], e.x, d0); d1 = fmaf(z1[4*c4+0], e.x, d1);
                d0 = fmaf(z0[4*c4+1], e.y, d0); d1 = fmaf(z1[4*c4+1], e.y, d1);
                d0 = fmaf(z0[4*c4+2], e.z, d0); d1 = fmaf(z1[4*c4+2], e.z, d1);
                d0 = fmaf(z0[4*c4+3], e.w, d0); d1 = fmaf(z1[4*c4+3], e.w, d1);
            }
            float nn = sn[kk];
            float dist0 = __fadd_rn(__fsub_rn(A0, __fmul_rn(2.0f, d0)), nn);
            float dist1 = __fadd_rn(__fsub_rn(A1, __fmul_rn(2.0f, d1)), nn);
            int k = kc*128 + kk;
            if (dist0 < best0) { best0 = dist0; bi0 = k; }
            if (dist1 < best1) { best1 = dist1; bi1 = k; }
        }
    }
    float* q0 = zq + n0*(64*4096) + hw0;
    float* q1 = zq + n1*(64*4096) + hw1;
    const float* e0 = emb + bi0*64;
    const float* e1 = emb + bi1*64;
    #pragma unroll
    for (int c = 0; c < 64; c++) {
        q0[c*4096] = __ldg(e0 + c);
        q1[c*4096] = __ldg(e1 + c);
    }
}

// ---------------- d1: convT 64->32 k3 s1 p1 == conv with flipped w ----------------
// block 64 thr: tid&3 = spg (4 x 16), tid>>2 = row (16 rows); grid (4, N, 4)
__global__ void __launch_bounds__(64) k_d1(const float* __restrict__ zq,
                                           const float* __restrict__ w,
                                           const float* __restrict__ b) {
    __shared__ float ws[8*64*9];
    int tid = threadIdx.x;
    int ocg = blockIdx.z;
    for (int t = tid; t < 8*64*9; t += 64) {
        int i  = t / 576;
        int rm = t - i*576;
        int ic = rm / 9;
        int kk = rm - ic*9;
        int kh = kk / 3, kw = kk - kh*3;
        int oc = ocg*8 + i;
        ws[t] = w[((ic*32 + oc)*3 + (2 - kh))*3 + (2 - kw)];  // (in,out,kh,kw) flipped
    }
    __syncthreads();

    int spg = tid & 3, r = tid >> 2;
    int n = blockIdx.y;
    int oh = blockIdx.x*16 + r;
    int ow0 = spg*16;

    float acc[8][16];
    #pragma unroll
    for (int i = 0; i < 8; i++)
        #pragma unroll
        for (int j = 0; j < 16; j++) acc[i][j] = 0.f;

    const float* inn = zq + n*(64*4096);
    for (int ic = 0; ic < 64; ic++) {
        const float* ip = inn + ic*4096;
        for (int kh = 0; kh < 3; kh++) {
            int ih = oh - 1 + kh;
            if ((unsigned)ih >= 64u) continue;
            float rv[18];
            const float* row = ip + ih*64;
            #pragma unroll
            for (int t = 0; t < 18; t++) {
                int iw = ow0 - 1 + t;
                rv[t] = ((unsigned)iw < 64u) ? __ldg(row + iw) : 0.f;
            }
            #pragma unroll
            for (int kw = 0; kw < 3; kw++)
                #pragma unroll
                for (int i = 0; i < 8; i++) {
                    float wv = ws[(i*64 + ic)*9 + kh*3 + kw];
                    #pragma unroll
                    for (int j = 0; j < 16; j++)
                        acc[i][j] = fmaf(rv[j + kw], wv, acc[i][j]);
                }
        }
    }
    #pragma unroll
    for (int i = 0; i < 8; i++) {
        int oc = ocg*8 + i;
        float bb = __ldg(b + oc);
        float* op = g_d1 + ((n*32 + oc)*64 + oh)*64 + ow0;
        #pragma unroll
        for (int j = 0; j < 16; j++) {
            float v = acc[i][j] + bb;
            op[j] = v > 0.f ? v : 0.f;
        }
    }
}

// ---------------- d2: convT 32->64, k4 s2 p1, 64->128, ReLU ----------------
// block 64: tid&3 = spg (4 x 32), tid>>2 = row (16); grid (8, N, 16)
__global__ void __launch_bounds__(64) k_d2(const float* __restrict__ w,
                                           const float* __restrict__ b) {
    __shared__ float ws[2048];   // [ic][i(4)][16]
    int tid = threadIdx.x;
    int ocg = blockIdx.z;
    for (int t = tid; t < 2048; t += 64) {
        int ic = t >> 6;
        int i  = (t >> 4) & 3;
        int kk = t & 15;
        ws[t] = w[(ic*64 + ocg*4 + i)*16 + kk];
    }
    __syncthreads();

    int spg = tid & 3, r = tid >> 2;
    int n = blockIdx.y;
    int oh = blockIdx.x*16 + r;
    int ow0 = spg*32;

    float acc[4][32];
    #pragma unroll
    for (int i = 0; i < 4; i++)
        #pragma unroll
        for (int j = 0; j < 32; j++) acc[i][j] = 0.f;

    int p = (oh + 1) & 1;
    int ih1 = (oh + 1 - p) >> 1;
    int ih2 = ih1 - 1;
    bool h1ok = (unsigned)ih1 < 64u, h2ok = (unsigned)ih2 < 64u;
    const float* inn = g_d1 + n*(32*4096);

    for (int ic = 0; ic < 32; ic++) {
        const float* ip = inn + ic*4096;
        float rv1[18], rv2[18];
        int iwb = (ow0 >> 1) - 1;
        #pragma unroll
        for (int t = 0; t < 18; t++) {
            int iw = iwb + t;
            bool wok = (unsigned)iw < 64u;
            rv1[t] = (wok && h1ok) ? __ldg(ip + ih1*64 + iw) : 0.f;
            rv2[t] = (wok && h2ok) ? __ldg(ip + ih2*64 + iw) : 0.f;
        }
        const float* wp = &ws[ic*64];
        #pragma unroll
        for (int i = 0; i < 4; i++) {
            const float* wpi = wp + i*16;
            float w00 = wpi[p*4 + 0], w02 = wpi[p*4 + 2];
            float w01 = wpi[p*4 + 1], w03 = wpi[p*4 + 3];
            float w20 = wpi[(p+2)*4 + 0], w22 = wpi[(p+2)*4 + 2];
            float w21 = wpi[(p+2)*4 + 1], w23 = wpi[(p+2)*4 + 3];
            #pragma unroll
            for (int j = 0; j < 32; j++) {
                const int q = (j + 1) & 1;
                const int s = ((j + 1) >> 1) + 1;
                float v = acc[i][j];
                if (q == 0) {
                    v = fmaf(rv1[s],   w00, v);
                    v = fmaf(rv1[s-1], w02, v);
                    v = fmaf(rv2[s],   w20, v);
                    v = fmaf(rv2[s-1], w22, v);
                } else {
                    v = fmaf(rv1[s],   w01, v);
                    v = fmaf(rv1[s-1], w03, v);
                    v = fmaf(rv2[s],   w21, v);
                    v = fmaf(rv2[s-1], w23, v);
                }
                acc[i][j] = v;
            }
        }
    }
    #pragma unroll
    for (int i = 0; i < 4; i++) {
        int oc = ocg*4 + i;
        float bb = __ldg(b + oc);
        float* op = g_d2 + ((n*64 + oc)*128 + oh)*128 + ow0;
        #pragma unroll
        for (int j = 0; j < 32; j++) {
            float v = acc[i][j] + bb;
            op[j] = v > 0.f ? v : 0.f;
        }
    }
}

// ---------------- d3: convT 64->1, k4 s2 p1, 128->256, no ReLU ----------------
// block 64: tid&15 = owg (16 x 16), tid>>4 = ohg (4 x 4 rows); grid (16, N)
__global__ void __launch_bounds__(64) k_d3(const float* __restrict__ w,
                                           const float* __restrict__ b,
                                           float* __restrict__ out) {
    __shared__ float ws[1024];
    int tid = threadIdx.x;
    for (int t = tid; t < 1024; t += 64) ws[t] = w[t];
    __syncthreads();

    int owg = tid & 15, ohg = tid >> 4;
    int n = blockIdx.y;
    int ob = blockIdx.x*16 + ohg*4;
    int ow0 = owg*16;

    float acc[4][16];
    #pragma unroll
    for (int i = 0; i < 4; i++)
        #pragma unroll
        for (int j = 0; j < 16; j++) acc[i][j] = 0.f;

    int ihb = (ob >> 1) - 1;
    int iwb = (ow0 >> 1) - 1;
    const float* inn = g_d2 + n*(64*16384);

    for (int ic = 0; ic < 64; ic++) {
        const float* ip = inn + ic*16384;
        float rv[4][10];
        #pragma unroll
        for (int rr = 0; rr < 4; rr++) {
            int ih = ihb + rr;
            bool hok = (unsigned)ih < 128u;
            const float* row = ip + ih*128;
            #pragma unroll
            for (int t = 0; t < 10; t++) {
                int iw = iwb + t;
                rv[rr][t] = (hok && (unsigned)iw < 128u) ? __ldg(row + iw) : 0.f;
            }
        }
        float wr[16];
        #pragma unroll
        for (int t = 0; t < 16; t++) wr[t] = ws[ic*16 + t];

        #pragma unroll
        for (int rr = 0; rr < 4; rr++) {
            const int p = (rr + 1) & 1;
            const int rel1 = ((rr + 1) >> 1) + 1;
            const int rel2 = rel1 - 1;
            #pragma unroll
            for (int j = 0; j < 16; j++) {
                const int q = (j + 1) & 1;
                const int s = ((j + 1) >> 1) + 1;
                float v = acc[rr][j];
                v = fmaf(rv[rel1][s],   wr[p*4 + q],       v);
                v = fmaf(rv[rel1][s-1], wr[p*4 + q + 2],   v);
                v = fmaf(rv[rel2][s],   wr[(p+2)*4 + q],   v);
                v = fmaf(rv[rel2][s-1], wr[(p+2)*4 + q+2], v);
                acc[rr][j] = v;
            }
        }
    }
    float bb = __ldg(b);
    #pragma unroll
    for (int rr = 0; rr < 4; rr++) {
        float* op = out + n*65536 + (ob + rr)*256 + ow0;
        #pragma unroll
        for (int j = 0; j < 16; j++) op[j] = acc[rr][j] + bb;
    }
}

// ---------------- launch ----------------
extern "C" void kernel_launch(void* const* d_in, const int* in_sizes, int n_in,
                              void* d_out, int out_size) {
    const float* x   = (const float*)d_in[0];
    const float* e1w = (const float*)d_in[1];  const float* e1b = (const float*)d_in[2];
    const float* e2w = (const float*)d_in[3];  const float* e2b = (const float*)d_in[4];
    const float* e3w = (const float*)d_in[5];  const float* e3b = (const float*)d_in[6];
    const float* emb = (const float*)d_in[7];
    const float* d1w = (const float*)d_in[8];  const float* d1b = (const float*)d_in[9];
    const float* d2w = (const float*)d_in[10]; const float* d2b = (const float*)d_in[11];
    const float* d3w = (const float*)d_in[12]; const float* d3b = (const float*)d_in[13];

    float* out  = (float*)d_out;
    float* xhat = out;                          // 64*1*256*256   = 4194304
    float* ze   = out + 4194304;                // 64*64*64*64    = 16777216
    float* zq   = out + 4194304 + 16777216;     // 64*64*64*64

    k_enorm<<<1, 512>>>(emb);
    k_e1<<<dim3(128, 4, NB), 128>>>(x, e1w, e1b);
    k_e2<<<dim3(16, 8, NB), 64>>>(e2w, e2b);
    k_e3<<<dim3(16, 8, NB), 64>>>(e3w, e3b, ze);
    k_vq<<<1024, 128>>>(ze, emb, zq);
    k_d1<<<dim3(4, NB, 4), 64>>>(zq, d1w, d1b);
    k_d2<<<dim3(8, NB, 16), 64>>>(d2w, d2b);
    k_d3<<<dim3(16, NB), 64>>>(d3w, d3b, xhat);
}